// round 6
// baseline (speedup 1.0000x reference)
#include <cuda_runtime.h>

#define IN_DIM    20
#define HID       6
#define OUT_DIM   6
#define THREADS   128
#define NWARPS    (THREADS / 32)
#define WT_ROWS   64                         // rows per warp-tile (2 per lane)
#define WT_F4     (WT_ROWS * IN_DIM / 4)     // 320 float4 per warp-tile
#define F4_PL     (WT_F4 / 32)               // 10 float4 per lane
#define WT_FLOATS (WT_ROWS * IN_DIM)         // 1280 floats = 5120 B

// weights in constant memory: warp-uniform LDCU -> UR operands, off the smem crossbar
__constant__ __align__(16) float cW1[HID * IN_DIM];   // [6][20]
__constant__ __align__(16) float cW2[HID * HID];      // [6][6]
__constant__ __align__(16) float cW5[OUT_DIM * HID];  // [6][6]

__device__ __forceinline__ unsigned smem_u32(const void* p) {
    return (unsigned)__cvta_generic_to_shared(p);
}
__device__ __forceinline__ void cp16(unsigned dst, const void* src) {
    asm volatile("cp.async.cg.shared.global [%0], [%1], 16;\n" :: "r"(dst), "l"(src));
}
__device__ __forceinline__ void cp_commit() {
    asm volatile("cp.async.commit_group;\n" ::: "memory");
}
template <int N>
__device__ __forceinline__ void cp_wait() {
    asm volatile("cp.async.wait_group %0;\n" :: "n"(N) : "memory");
}
__device__ __forceinline__ void stg_cs_v2(float2* p, float2 v) {
    asm volatile("st.global.cs.v2.f32 [%0], {%1, %2};\n" :: "l"(p), "f"(v.x), "f"(v.y));
}

// sigmoid(z) = 0.5 * tanh(0.5 z) + 0.5   -> 1 MUFU.TANH + FMUL + FFMA
__device__ __forceinline__ float sigmoid_t(float z) {
    float th;
    asm("tanh.approx.f32 %0, %1;" : "=f"(th) : "f"(z * 0.5f));
    return fmaf(th, 0.5f, 0.5f);
}

__global__ __launch_bounds__(THREADS, 5)
void mlp3_kernel(const float* __restrict__ x,
                 float* __restrict__ out,        // [B, OUT]
                 int B, int nwt)
{
    // per-warp double buffers: [NWARPS][2][WT_FLOATS]
    extern __shared__ __align__(16) float sX[];

    const int t = threadIdx.x;
    const int w = t >> 5;
    const int l = t & 31;

    const size_t total_f4 = ((size_t)B * IN_DIM) >> 2;
    float* mybuf0 = &sX[(size_t)(w * 2) * WT_FLOATS];

    // warp-local stage: 10 contiguous float4 per lane (fully coalesced)
    auto stage = [&](int wt, int buf) {
        size_t base_f4 = (size_t)wt * WT_F4;
        const float4* src = reinterpret_cast<const float4*>(x) + base_f4;
        unsigned dst = smem_u32(mybuf0 + (size_t)buf * WT_FLOATS);
#pragma unroll
        for (int q = 0; q < F4_PL; ++q) {
            int idx = l + q * 32;
            if (base_f4 + (size_t)idx < total_f4)
                cp16(dst + (unsigned)idx * 16, src + idx);
        }
    };

    const int wstride = gridDim.x * NWARPS;
    int wt = blockIdx.x * NWARPS + w;

    if (wt < nwt) stage(wt, 0);
    cp_commit();

    int buf = 0;
    for (; wt < nwt; wt += wstride, buf ^= 1) {
        int nxt = wt + wstride;
        if (nxt < nwt) stage(nxt, buf ^ 1);
        cp_commit();
        cp_wait<1>();          // our own warp's current tile is complete
        __syncwarp();          // lane-visibility of peer lanes' staged bytes

        const float* xb = mybuf0 + (size_t)buf * WT_FLOATS;
        const int r0 = wt * WT_ROWS + l;        // row A
        const int r1 = r0 + 32;                 // row B

        // ---- both rows from smem: 2 x 5 LDS.128, conflict-free in-phase ----
        float4 xa[5], xbv[5];
        const float4* pa = reinterpret_cast<const float4*>(&xb[l * IN_DIM]);
        const float4* pb = reinterpret_cast<const float4*>(&xb[(l + 32) * IN_DIM]);
#pragma unroll
        for (int q = 0; q < 5; ++q) { xa[q] = pa[q]; xbv[q] = pb[q]; }

        // ---- layer 1: weights from constant (uniform LDCU), shared by both rows ----
        float h1a[6], h1b[6];
#pragma unroll
        for (int j = 0; j < HID; ++j) {
            const float4* wr = reinterpret_cast<const float4*>(&cW1[j * IN_DIM]);
            float a = 0.0f, b = 0.0f;
#pragma unroll
            for (int q = 0; q < 5; ++q) {
                float4 wv = wr[q];
                a = fmaf(xa[q].x,  wv.x, a); b = fmaf(xbv[q].x, wv.x, b);
                a = fmaf(xa[q].y,  wv.y, a); b = fmaf(xbv[q].y, wv.y, b);
                a = fmaf(xa[q].z,  wv.z, a); b = fmaf(xbv[q].z, wv.z, b);
                a = fmaf(xa[q].w,  wv.w, a); b = fmaf(xbv[q].w, wv.w, b);
            }
            h1a[j] = sigmoid_t(a);
            h1b[j] = sigmoid_t(b);
        }

        // ---- layer 2 ----
        float h2a[6], h2b[6];
#pragma unroll
        for (int j = 0; j < HID; ++j) {
            float a = 0.0f, b = 0.0f;
#pragma unroll
            for (int k = 0; k < HID; ++k) {
                float wv = cW2[j * HID + k];
                a = fmaf(h1a[k], wv, a);
                b = fmaf(h1b[k], wv, b);
            }
            h2a[j] = sigmoid_t(a);
            h2b[j] = sigmoid_t(b);
        }

        // ---- layer 3 (linear) ----
        float oa[OUT_DIM], ob[OUT_DIM];
#pragma unroll
        for (int j = 0; j < OUT_DIM; ++j) {
            float a = 0.0f, b = 0.0f;
#pragma unroll
            for (int k = 0; k < HID; ++k) {
                float wv = cW5[j * HID + k];
                a = fmaf(h2a[k], wv, a);
                b = fmaf(h2b[k], wv, b);
            }
            oa[j] = a; ob[j] = b;
        }

        if (r0 < B) {
            float2* op = reinterpret_cast<float2*>(out + (size_t)r0 * OUT_DIM);
            stg_cs_v2(op + 0, make_float2(oa[0], oa[1]));
            stg_cs_v2(op + 1, make_float2(oa[2], oa[3]));
            stg_cs_v2(op + 2, make_float2(oa[4], oa[5]));
        }
        if (r1 < B) {
            float2* op = reinterpret_cast<float2*>(out + (size_t)r1 * OUT_DIM);
            stg_cs_v2(op + 0, make_float2(ob[0], ob[1]));
            stg_cs_v2(op + 1, make_float2(ob[2], ob[3]));
            stg_cs_v2(op + 2, make_float2(ob[4], ob[5]));
        }
        // no block barrier: buffers are warp-private; same-warp program order
        // makes the WAR on restage safe.
    }
}

extern "C" void kernel_launch(void* const* d_in, const int* in_sizes, int n_in,
                              void* d_out, int out_size)
{
    const float* x  = (const float*)d_in[0];
    const float* W1 = (const float*)d_in[1];
    const float* W2 = (const float*)d_in[2];
    const float* W5 = (const float*)d_in[3];
    float* out = (float*)d_out;

    const int B = in_sizes[0] / IN_DIM;
    const int nwt = (B + WT_ROWS - 1) / WT_ROWS;

    // weights -> constant memory (D2D async copies; graph-capturable memcpy nodes)
    cudaMemcpyToSymbolAsync(cW1, W1, HID * IN_DIM * sizeof(float), 0,
                            cudaMemcpyDeviceToDevice, 0);
    cudaMemcpyToSymbolAsync(cW2, W2, HID * HID * sizeof(float), 0,
                            cudaMemcpyDeviceToDevice, 0);
    cudaMemcpyToSymbolAsync(cW5, W5, OUT_DIM * HID * sizeof(float), 0,
                            cudaMemcpyDeviceToDevice, 0);

    const size_t smem_bytes = (size_t)NWARPS * 2 * WT_FLOATS * sizeof(float);  // 40 KB
    static bool attr_set = false;
    if (!attr_set) {
        cudaFuncSetAttribute(mlp3_kernel,
                             cudaFuncAttributeMaxDynamicSharedMemorySize,
                             (int)smem_bytes);
        attr_set = true;
    }

    int blocks = 148 * 5;                 // persistent: 5 CTAs/SM, 20 warp-pipelines
    int max_blocks = (nwt + NWARPS - 1) / NWARPS;
    if (blocks > max_blocks) blocks = max_blocks;
    if (blocks < 1) blocks = 1;

    mlp3_kernel<<<blocks, THREADS, smem_bytes>>>(x, out, B, nwt);
}